// round 9
// baseline (speedup 1.0000x reference)
#include <cuda_runtime.h>
#include <cuda_fp16.h>
#include <math.h>
#include <stdint.h>

// Shapes (fixed)
#define HW_DIM  1024
#define C_DIM   256
#define N_TOK   32768
#define K_CODES 1024
#define Z_ELEMS 8388608
#define BETA_F  0.25f

// tiling: CTA = 512 threads, 128 tokens x 1024 codes; 32 chunks of 32 codes
#define MT      128
#define NCTA    (N_TOK / MT)     // 256
#define NCH     32
#define CHUNKS  (K_CODES / NCH)  // 32
#define KSTEPS  16

// smem layout (bytes)
#define AROWB   528              // 264 halves per row (528%128=16, ldsm clean)
#define AH_OFF  0                // 128*528 = 67584
#define AL_OFF  67584            // ends 135168
#define RING_OFF 135168          // 2 slots x 32768 (32 codes x 1024B swizzled)
#define RSLOT   32768
#define NS_OFF  200704           // 1024 floats -> 204800
#define SMEM_TOTAL 204800
// post-mainloop scratch aliases the ring:
#define CV_OFF  RING_OFF                 // 256 floats
#define CI_OFF  (RING_OFF + 1024)        // 256 ints
#define KF_OFF  (RING_OFF + 2048)        // 128 ints
#define RED_OFF (RING_OFF + 2560)        // 512 floats

static __device__ int    g_counts[K_CODES];
static __device__ float  g_norms[K_CODES];
static __device__ float  g_partials[NCTA];
// pre-split codebook: row = 1024B = 32 k-blocks of [hi x8 | lo x8] halves
static __device__ __half g_cbi[K_CODES * 512];

// ---------------------------------------------------------------------------
__device__ __forceinline__ uint32_t smem_u32(const void* p) {
    uint32_t a;
    asm("{ .reg .u64 T; cvta.to.shared.u64 T, %1; cvt.u32.u64 %0, T; }"
        : "=r"(a) : "l"(p));
    return a;
}
__device__ __forceinline__ void ldsm4(uint32_t addr, uint32_t r[4]) {
    asm volatile("ldmatrix.sync.aligned.m8n8.x4.shared.b16 {%0,%1,%2,%3}, [%4];"
                 : "=r"(r[0]), "=r"(r[1]), "=r"(r[2]), "=r"(r[3]) : "r"(addr));
}
__device__ __forceinline__ void mma_f16(float c[4], const uint32_t a[4],
                                        uint32_t b0, uint32_t b1) {
    asm volatile(
        "mma.sync.aligned.m16n8k16.row.col.f32.f16.f16.f32 "
        "{%0,%1,%2,%3}, {%4,%5,%6,%7}, {%8,%9}, {%0,%1,%2,%3};"
        : "+f"(c[0]), "+f"(c[1]), "+f"(c[2]), "+f"(c[3])
        : "r"(a[0]), "r"(a[1]), "r"(a[2]), "r"(a[3]), "r"(b0), "r"(b1));
}
#define CP_ASYNC16(dst, src) \
    asm volatile("cp.async.cg.shared.global [%0], [%1], 16;" :: "r"(dst), "l"(src))
#define CP_COMMIT() asm volatile("cp.async.commit_group;" ::: "memory")
#define CP_WAIT1()  asm volatile("cp.async.wait_group 1;" ::: "memory")
#define CP_WAIT0()  asm volatile("cp.async.wait_group 0;" ::: "memory")

// ---------------------------------------------------------------------------
// prep: interleaved hi/lo codebook (unscaled residual) + norms + zero counts
__global__ void prep_kernel(const float* __restrict__ cb) {
    __shared__ float red[8];
    const int code = blockIdx.x;
    const int c    = threadIdx.x;
    float v = cb[code * C_DIM + c];
    __half hi = __float2half_rn(v);
    __half lo = __float2half_rn(v - __half2float(hi));
    int base = code * 512 + (c >> 3) * 16 + (c & 7);
    g_cbi[base]     = hi;
    g_cbi[base + 8] = lo;
    float s = v * v;
    #pragma unroll
    for (int off = 16; off > 0; off >>= 1)
        s += __shfl_down_sync(0xffffffffu, s, off);
    if ((c & 31) == 0) red[c >> 5] = s;
    __syncthreads();
    if (c == 0) {
        float t = 0.f;
        #pragma unroll
        for (int i = 0; i < 8; i++) t += red[i];
        g_norms[code]  = t;
        g_counts[code] = 0;
    }
}

// ---------------------------------------------------------------------------
// fused split-fp16 GEMM-argmin (+gather +loss), 512 threads / 16 warps.
// Warps: tg = warp>>1 (8 groups x 16 tokens), cg = warp&1 (2 x 16 codes).
// Warp tile = 16 tok x 16 codes; 4 independent HMMA chains per warp.
__global__ __launch_bounds__(512, 1)
void argmin_fused(const float* __restrict__ z, const float* __restrict__ cb,
                  float* __restrict__ out) {
    extern __shared__ char smem[];
    const uint32_t sb = smem_u32(smem);
    float* ns = (float*)(smem + NS_OFF);

    const int tid  = threadIdx.x;
    const int warp = tid >> 5;
    const int lane = tid & 31;
    const int tg   = warp >> 1;      // 0..7, 16 tokens each
    const int cg   = warp & 1;       // 16-code half of 32-chunk
    const int g    = lane >> 2;
    const int t    = lane & 3;

    const int n0  = blockIdx.x * MT;
    const int b   = n0 >> 10;
    const int hw0 = n0 & 1023;
    const float* zb = z + (size_t)b * (C_DIM * HW_DIM) + hw0;

    // ---- B prefetch: chunk = 32 codes x 1024B rows, XOR-swizzled ----------
    auto prefetch = [&](int p) {
        const char* src = (const char*)g_cbi + (size_t)p * RSLOT;
        uint32_t dst0 = sb + RING_OFF + (uint32_t)((p & 1) * RSLOT);
        #pragma unroll
        for (int it = 0; it < 4; it++) {
            int i    = it * 512 + tid;
            int code = i >> 6;
            int seg  = i & 63;
            uint32_t dst = dst0 + (uint32_t)(code * 1024 + ((seg ^ (code & 7)) << 4));
            CP_ASYNC16(dst, src + (size_t)i * 16);
        }
    };
    prefetch(0); CP_COMMIT();
    prefetch(1); CP_COMMIT();

    // ---- stage A: hi and lo (unscaled residual), coalesced over tokens ----
    for (int it = 0; it < 64; it++) {
        int i  = it * 512 + tid;
        int tk = i & 127;
        int c  = i >> 7;
        float a = zb[(size_t)c * HW_DIM + tk];
        __half hi = __float2half_rn(a);
        __half lo = __float2half_rn(a - __half2float(hi));
        *(__half*)(smem + AH_OFF + tk * AROWB + c * 2) = hi;
        *(__half*)(smem + AL_OFF + tk * AROWB + c * 2) = lo;
    }
    #pragma unroll
    for (int it = 0; it < 2; it++) ns[it * 512 + tid] = g_norms[it * 512 + tid];

    // per-lane ldsm addresses
    const uint32_t aH = sb + AH_OFF
        + (uint32_t)((tg * 16 + (lane & 15)) * AROWB + (lane >> 4) * 16);
    const uint32_t aL = aH + (uint32_t)(AL_OFF - AH_OFF);
    const int bcode = lane & 7;
    const int bgrp  = lane >> 3;     // seg-matrix index 0..3
    uint32_t brow[2];
    #pragma unroll
    for (int nb = 0; nb < 2; nb++)
        brow[nb] = (uint32_t)((cg * 16 + nb * 8 + bcode) * 1024);

    float bestv[2];
    int   besti[2];
    #pragma unroll
    for (int s = 0; s < 2; s++) { bestv[s] = 3.4e38f; besti[s] = 0; }

    for (int p = 0; p < CHUNKS; p++) {
        if (p == CHUNKS - 1) CP_WAIT0(); else CP_WAIT1();
        __syncthreads();

        const uint32_t pbase = sb + RING_OFF + (uint32_t)((p & 1) * RSLOT);

        float hh[2][4], md[2][4];
        #pragma unroll
        for (int nb = 0; nb < 2; nb++)
            #pragma unroll
            for (int q = 0; q < 4; q++) { hh[nb][q] = 0.f; md[nb][q] = 0.f; }

        #pragma unroll
        for (int ks = 0; ks < KSTEPS; ks++) {
            uint32_t ahf[4], alf[4];
            ldsm4(aH + (uint32_t)(ks * 32), ahf);
            ldsm4(aL + (uint32_t)(ks * 32), alf);
            #pragma unroll
            for (int nb = 0; nb < 2; nb++) {
                // one ldsm4 -> [bh k0-7][bl k0-7][bh k8-15][bl k8-15], 8 codes
                uint32_t bb[4];
                ldsm4(pbase + brow[nb]
                      + (uint32_t)(((4 * ks + bgrp) ^ bcode) << 4), bb);
                mma_f16(hh[nb], ahf, bb[0], bb[2]);   // ah*bh
                mma_f16(md[nb], ahf, bb[1], bb[3]);   // ah*bl
                mma_f16(md[nb], alf, bb[0], bb[2]);   // al*bh
            }
        }

        __syncthreads();                 // all reads done before refill
        if (p + 2 < CHUNKS) { prefetch(p + 2); CP_COMMIT(); }

        // epilogue: dist = |e|^2 - 2*hh - 2*md
        #pragma unroll
        for (int nb = 0; nb < 2; nb++) {
            int cl = cg * 16 + nb * 8 + 2 * t;
            int code0 = p * NCH + cl;
            float nk0 = ns[code0];
            float nk1 = ns[code0 + 1];
            float d00 = nk0 - 2.f * hh[nb][0] - 2.f * md[nb][0];
            float d01 = nk1 - 2.f * hh[nb][1] - 2.f * md[nb][1];
            float d10 = nk0 - 2.f * hh[nb][2] - 2.f * md[nb][2];
            float d11 = nk1 - 2.f * hh[nb][3] - 2.f * md[nb][3];
            if (d00 < bestv[0]) { bestv[0] = d00; besti[0] = code0; }
            if (d01 < bestv[0]) { bestv[0] = d01; besti[0] = code0 + 1; }
            if (d10 < bestv[1]) { bestv[1] = d10; besti[1] = code0; }
            if (d11 < bestv[1]) { bestv[1] = d11; besti[1] = code0 + 1; }
        }
    }

    // lane-reduce across t (lanes 4g..4g+3 share a token row)
    #pragma unroll
    for (int s = 0; s < 2; s++) {
        #pragma unroll
        for (int m = 1; m <= 2; m <<= 1) {
            float v2 = __shfl_xor_sync(0xffffffffu, bestv[s], m);
            int   i2 = __shfl_xor_sync(0xffffffffu, besti[s], m);
            if (v2 < bestv[s] || (v2 == bestv[s] && i2 < besti[s])) {
                bestv[s] = v2; besti[s] = i2;
            }
        }
    }

    // cross-warp merge (scratch aliases the dead ring region)
    float* candv = (float*)(smem + CV_OFF);
    int*   candi = (int*)(smem + CI_OFF);
    int*   kf    = (int*)(smem + KF_OFF);
    if (t == 0) {
        #pragma unroll
        for (int s = 0; s < 2; s++) {
            int tok = tg * 16 + s * 8 + g;
            candv[tok * 2 + cg] = bestv[s];
            candi[tok * 2 + cg] = besti[s];
        }
    }
    __syncthreads();
    if (tid < MT) {
        float v0 = candv[tid * 2], v1 = candv[tid * 2 + 1];
        int   i0 = candi[tid * 2], i1 = candi[tid * 2 + 1];
        int bi;
        if (v1 < v0 || (v1 == v0 && i1 < i0)) bi = i1; else bi = i0;
        kf[tid] = bi;
        atomicAdd(&g_counts[bi], 1);
    }
    __syncthreads();

    // -------- fused gather + loss: 128 tokens x 256 channels ---------------
    {
        const int tok = tid & 127;
        const int ch0 = (tid >> 7) * 64;           // 4 chunks of 64 channels
        const int k   = kf[tok];
        const float4* crow = (const float4*)(cb + (size_t)k * C_DIM + ch0);
        const float* zp = zb + (size_t)ch0 * HW_DIM + tok;
        float* op = out + (size_t)b * (C_DIM * HW_DIM) + hw0
                        + (size_t)ch0 * HW_DIM + tok;
        float s = 0.f;
        #pragma unroll 8
        for (int j = 0; j < 16; j++) {
            float4 e = crow[j];
            int c = j * 4;
            float d0 = e.x - zp[(c + 0) * HW_DIM];
            float d1 = e.y - zp[(c + 1) * HW_DIM];
            float d2 = e.z - zp[(c + 2) * HW_DIM];
            float d3 = e.w - zp[(c + 3) * HW_DIM];
            s += d0 * d0 + d1 * d1 + d2 * d2 + d3 * d3;
            op[(c + 0) * HW_DIM] = e.x;
            op[(c + 1) * HW_DIM] = e.y;
            op[(c + 2) * HW_DIM] = e.z;
            op[(c + 3) * HW_DIM] = e.w;
        }
        float* red = (float*)(smem + RED_OFF);
        red[tid] = s;
        __syncthreads();
        for (int off = 256; off > 0; off >>= 1) {
            if (tid < off) red[tid] += red[tid + off];
            __syncthreads();
        }
        if (tid == 0) g_partials[blockIdx.x] = red[0];
    }
}

// ---------------------------------------------------------------------------
__global__ void finalize_kernel(float* __restrict__ out, int out_size) {
    __shared__ float s1[1024];
    __shared__ float s2[1024];
    const int tid = threadIdx.x;
    float ls = (tid < NCTA) ? g_partials[tid] : 0.f;
    float p  = (float)g_counts[tid] * (1.0f / (float)N_TOK);
    float pc = fmaxf(p, 1e-10f);
    s1[tid] = ls;
    s2[tid] = pc * logf(pc);
    __syncthreads();
    for (int off = 512; off > 0; off >>= 1) {
        if (tid < off) { s1[tid] += s1[tid + off]; s2[tid] += s2[tid + off]; }
        __syncthreads();
    }
    if (tid == 0) {
        float mse = s1[0] * (1.0f / (float)Z_ELEMS);
        if (out_size >= Z_ELEMS + 1) out[Z_ELEMS]     = mse * (1.0f + BETA_F);
        if (out_size >= Z_ELEMS + 2) out[Z_ELEMS + 1] = expf(-s2[0]);
    }
}

// ---------------------------------------------------------------------------
extern "C" void kernel_launch(void* const* d_in, const int* in_sizes, int n_in,
                              void* d_out, int out_size) {
    const float* z  = (const float*)d_in[0];
    const float* cb = (const float*)d_in[1];
    float* out = (float*)d_out;

    cudaFuncSetAttribute(argmin_fused,
                         cudaFuncAttributeMaxDynamicSharedMemorySize, SMEM_TOTAL);

    prep_kernel<<<K_CODES, 256>>>(cb);
    argmin_fused<<<NCTA, 512, SMEM_TOTAL>>>(z, cb, out);
    finalize_kernel<<<1, 1024>>>(out, out_size);
}